// round 13
// baseline (speedup 1.0000x reference)
#include <cuda_runtime.h>
#include <math.h>

#define Bn 4096
#define Tn 64
#define Hn 64
#define BT (Bn*Tn)

typedef unsigned long long ull_t;

// ---------------- scratch (device globals; no allocation allowed) ----------------
__device__ float g_X[(size_t)BT*64];                 // MLP output [B*T,64], row r = b*T+t
__device__ float g_G[(size_t)2*Tn*Bn*256];           // gate preacts x@Wx+b : [dir][t][b][256]
__device__ float g_hall[(size_t)2*Bn*Tn*Hn];         // [s][t][h], s<B: fw, s>=B: bw (time-aligned)

// clamped fast activations: avoids __fdividef's undefined window (den in 2^126..2^128)
__device__ __forceinline__ float sigm(float x){
    x = fminf(fmaxf(x, -30.0f), 30.0f);
    return __fdividef(1.0f, 1.0f + __expf(-x));
}
__device__ __forceinline__ float tanh_f(float x){
    x = fminf(fmaxf(x, -15.0f), 15.0f);
    return 1.0f - __fdividef(2.0f, __expf(2.0f*x) + 1.0f);
}

// ---- packed f32x2 helpers (sm_103a) ----
__device__ __forceinline__ ull_t pk2(float lo, float hi){
    ull_t r; asm("mov.b64 %0, {%1,%2};" : "=l"(r) : "f"(lo), "f"(hi)); return r;
}
__device__ __forceinline__ void upk2(ull_t v, float &lo, float &hi){
    asm("mov.b64 {%0,%1}, %2;" : "=f"(lo), "=f"(hi) : "l"(v));
}
__device__ __forceinline__ void ffma2(ull_t &d, ull_t a, ull_t b){
    asm("fma.rn.f32x2 %0, %1, %2, %0;" : "+l"(d) : "l"(a), "l"(b));
}

// =====================================================================
// Kernel 1: fused MLP trunk (f32x2, pre-duplicated activation operands)
//   x1 = relu(LN(obs@W1+b1)); x2 = relu(LN([x1,action]@W2+b2)) -> g_X
// 256 threads, 64 rows/block in 4 iterations of 16 rows.
// Thread map: warp w owns rows {2w, 2w+1}; lane owns col pair j2=(lane*2).
// Activations stored as float2(v,v): ulonglong2 LDS.128 feeds ffma2 with
// zero pk2 MOVs in the hot loops. Layernorm reductions are warp-local.
// =====================================================================
__global__ void __launch_bounds__(256) mlp_kernel(
    const float* __restrict__ obs, const float* __restrict__ action,
    const float* __restrict__ W1, const float* __restrict__ b1, const float* __restrict__ gm1, const float* __restrict__ be1,
    const float* __restrict__ W2, const float* __restrict__ b2, const float* __restrict__ gm2, const float* __restrict__ be2)
{
    extern __shared__ float sm[];
    float*  s_W1  = sm;                     // 128*64 = 8192 floats
    float*  s_W2  = s_W1 + 8192;            // 96*64  = 6144
    float*  s_p   = s_W2 + 6144;            // 6*64   = 384
    float2* s_ob2 = (float2*)(s_p + 384);   // 16*128 float2 = 4096 floats
    float2* s_in2 = s_ob2 + 2048;           // 16*96  float2 = 3072 floats
    // total 21888 floats = 87552 B

    int tid = threadIdx.x;
    for (int i = tid; i < 8192; i += 256) s_W1[i] = W1[i];
    for (int i = tid; i < 6144; i += 256) s_W2[i] = W2[i];
    if (tid < 64) {
        s_p[tid]     = b1[tid];  s_p[64+tid]  = gm1[tid]; s_p[128+tid] = be1[tid];
        s_p[192+tid] = b2[tid];  s_p[256+tid] = gm2[tid]; s_p[320+tid] = be2[tid];
    }
    __syncthreads();

    int lane = tid & 31, w = tid >> 5;
    int j2 = lane * 2;
    int r0 = w * 2;

    for (int it = 0; it < 4; ++it) {
        int rowbase = blockIdx.x * 64 + it * 16;
        if (it) __syncthreads();   // previous iteration's smem readers done
        for (int i = tid; i < 2048; i += 256){
            float v = obs[(size_t)rowbase*128 + i];
            s_ob2[i] = make_float2(v, v);
        }
        for (int i = tid; i < 512;  i += 256){
            float v = action[(size_t)rowbase*32 + i];
            s_in2[(i>>5)*96 + 64 + (i&31)] = make_float2(v, v);
        }
        __syncthreads();

        // ---- layer 1: z = obs@W1 + b1 (packed col pairs, 2 rows/thread) ----
        ull_t acc0 = pk2(s_p[j2], s_p[j2+1]);
        ull_t acc1 = acc0;
        const float2* a0p = &s_ob2[r0*128];
        const float2* a1p = &s_ob2[(r0+1)*128];
        #pragma unroll 8
        for (int k = 0; k < 128; k += 2){
            ulonglong2 a0 = *(const ulonglong2*)&a0p[k];   // (a[k],a[k]),(a[k+1],a[k+1])
            ulonglong2 a1 = *(const ulonglong2*)&a1p[k];
            ull_t w0 = *(const ull_t*)&s_W1[(k+0)*64 + j2];
            ull_t w1 = *(const ull_t*)&s_W1[(k+1)*64 + j2];
            ffma2(acc0, a0.x, w0); ffma2(acc1, a1.x, w0);
            ffma2(acc0, a0.y, w1); ffma2(acc1, a1.y, w1);
        }
        // warp-local layernorm for rows r0, r0+1
        {
            float v00,v01,v10,v11;
            upk2(acc0,v00,v01); upk2(acc1,v10,v11);
            float s0=v00+v01, q0=v00*v00+v01*v01;
            float s1=v10+v11, q1=v10*v10+v11*v11;
            #pragma unroll
            for (int o=16;o>0;o>>=1){
                s0+=__shfl_xor_sync(0xffffffffu,s0,o); q0+=__shfl_xor_sync(0xffffffffu,q0,o);
                s1+=__shfl_xor_sync(0xffffffffu,s1,o); q1+=__shfl_xor_sync(0xffffffffu,q1,o);
            }
            float m0=s0*(1.0f/64.0f), var0=q0*(1.0f/64.0f)-m0*m0, rs0=rsqrtf(var0+1e-12f);
            float m1=s1*(1.0f/64.0f), var1=q1*(1.0f/64.0f)-m1*m1, rs1=rsqrtf(var1+1e-12f);
            float ga=s_p[64+j2], gb=s_p[64+j2+1], ba=s_p[128+j2], bbv=s_p[128+j2+1];
            float o00 = fmaxf((v00-m0)*rs0*ga+ba,0.0f), o01 = fmaxf((v01-m0)*rs0*gb+bbv,0.0f);
            float o10 = fmaxf((v10-m1)*rs1*ga+ba,0.0f), o11 = fmaxf((v11-m1)*rs1*gb+bbv,0.0f);
            // duplicated pair store: one STS.128 per row
            *(float4*)&s_in2[r0*96 + j2]     = make_float4(o00,o00,o01,o01);
            *(float4*)&s_in2[(r0+1)*96 + j2] = make_float4(o10,o10,o11,o11);
        }
        __syncwarp();   // rows are warp-private: warp-level sync suffices

        // ---- layer 2: z = [x1,action]@W2 + b2 ----
        acc0 = pk2(s_p[192+j2], s_p[192+j2+1]);
        acc1 = acc0;
        const float2* i0p = &s_in2[r0*96];
        const float2* i1p = &s_in2[(r0+1)*96];
        #pragma unroll 8
        for (int k = 0; k < 96; k += 2){
            ulonglong2 a0 = *(const ulonglong2*)&i0p[k];
            ulonglong2 a1 = *(const ulonglong2*)&i1p[k];
            ull_t w0 = *(const ull_t*)&s_W2[(k+0)*64 + j2];
            ull_t w1 = *(const ull_t*)&s_W2[(k+1)*64 + j2];
            ffma2(acc0, a0.x, w0); ffma2(acc1, a1.x, w0);
            ffma2(acc0, a0.y, w1); ffma2(acc1, a1.y, w1);
        }
        {
            float v00,v01,v10,v11;
            upk2(acc0,v00,v01); upk2(acc1,v10,v11);
            float s0=v00+v01, q0=v00*v00+v01*v01;
            float s1=v10+v11, q1=v10*v10+v11*v11;
            #pragma unroll
            for (int o=16;o>0;o>>=1){
                s0+=__shfl_xor_sync(0xffffffffu,s0,o); q0+=__shfl_xor_sync(0xffffffffu,q0,o);
                s1+=__shfl_xor_sync(0xffffffffu,s1,o); q1+=__shfl_xor_sync(0xffffffffu,q1,o);
            }
            float m0=s0*(1.0f/64.0f), var0=q0*(1.0f/64.0f)-m0*m0, rs0=rsqrtf(var0+1e-12f);
            float m1=s1*(1.0f/64.0f), var1=q1*(1.0f/64.0f)-m1*m1, rs1=rsqrtf(var1+1e-12f);
            float ga=s_p[256+j2], gb=s_p[256+j2+1], ba=s_p[320+j2], bbv=s_p[320+j2+1];
            float2 o0 = make_float2(fmaxf((v00-m0)*rs0*ga+ba,0.0f), fmaxf((v01-m0)*rs0*gb+bbv,0.0f));
            float2 o1 = make_float2(fmaxf((v10-m1)*rs1*ga+ba,0.0f), fmaxf((v11-m1)*rs1*gb+bbv,0.0f));
            *(float2*)&g_X[(size_t)(rowbase + r0)*64 + j2]     = o0;
            *(float2*)&g_X[(size_t)(rowbase + r0 + 1)*64 + j2] = o1;
        }
    }
}

// =====================================================================
// Kernel 2: gate precompute  G[dir][t][b][0:256] = X[b*T+t] @ W_dir[0:64,:] + b_dir
// grid (BT/64, 2): one block = 64 rows x all 256 cols of one direction.
// sA stored PRE-DUPLICATED as float2(v,v): ulonglong2 LDS.128 yields two
// ready packed a-operands (2 k's) with ZERO pk2 MOVs in the hot loop.
// B operand loads fused to LDS.128 (two col-pairs per load).
// G stores use __stcs (evict-first): G is 536 MB stream-once data, keeping
// it out of L2 preserves residency for g_X re-reads and LSTM weights.
// 48 KB static smem -> 2 CTAs/SM to hide the per-chunk barriers.
// =====================================================================
__global__ void __launch_bounds__(256, 2) gemm_g_kernel(
    const float* __restrict__ Wf, const float* __restrict__ bf,
    const float* __restrict__ Wb, const float* __restrict__ bb)
{
    __shared__ float2 sA2[64*64];   // [row][k] = (x,x)  -> 32768 B
    __shared__ float  sB[64*64];    // sB[k*64+j]        -> 16384 B (total 48 KB static)
    int tid = threadIdx.x;
    int rb = blockIdx.x * 64;
    int dir = blockIdx.y;
    const float* W    = dir ? Wb : Wf;
    const float* bias = dir ? bb : bf;

    #pragma unroll
    for (int itld = 0; itld < 16; ++itld) {
        int idx = itld*256 + tid;
        int r = idx >> 6, k = idx & 63;
        float v = g_X[(size_t)(rb + r)*64 + k];
        sA2[r*64 + k] = make_float2(v, v);
    }

    int tx = tid & 15, ty = tid >> 4;

    for (int chunk = 0; chunk < 4; ++chunk){
        int colbase = chunk << 6;
        if (chunk) __syncthreads();          // prior chunk's sB readers done
        #pragma unroll
        for (int itld = 0; itld < 16; ++itld) {
            int idx = itld*256 + tid;
            int r = idx >> 6, k = idx & 63;
            sB[idx] = W[(size_t)r*256 + colbase + k];
        }
        float4 bia = *(const float4*)&bias[colbase + tx*4];   // this thread's 4 bias cols
        __syncthreads();                      // sB (and sA2 on first pass) visible

        ull_t acc2[4][2];
        #pragma unroll
        for (int i=0;i<4;i++){ acc2[i][0]=0ull; acc2[i][1]=0ull; }

        #pragma unroll 8
        for (int k=0;k<64;k+=2){
            ulonglong2 a2[4];                 // .x=(a[k],a[k]) .y=(a[k+1],a[k+1])
            #pragma unroll
            for (int i=0;i<4;i++) a2[i] = *(const ulonglong2*)&sA2[(ty*4+i)*64 + k];
            // both 4-col B slices as single LDS.128 each
            ulonglong2 b0 = *(const ulonglong2*)&sB[(k+0)*64 + tx*4];  // .x cols[0:2) .y cols[2:4)
            ulonglong2 b1 = *(const ulonglong2*)&sB[(k+1)*64 + tx*4];
            #pragma unroll
            for (int i=0;i<4;i++){
                ffma2(acc2[i][0], a2[i].x, b0.x);
                ffma2(acc2[i][1], a2[i].x, b0.y);
                ffma2(acc2[i][0], a2[i].y, b1.x);
                ffma2(acc2[i][1], a2[i].y, b1.y);
            }
        }

        #pragma unroll
        for (int i=0;i<4;i++){
            int r = rb + ty*4 + i;
            int b_ = r >> 6, t = r & 63;
            size_t base = (((size_t)dir*64 + t)*4096 + b_)*256 + colbase + tx*4;
            float4 v;
            float q0,q1,q2,q3;
            upk2(acc2[i][0], q0, q1);
            upk2(acc2[i][1], q2, q3);
            v.x = q0 + bia.x;
            v.y = q1 + bia.y;
            v.z = q2 + bia.z;
            v.w = q3 + bia.w;
            __stcs((float4*)&g_G[base], v);   // stream-once: evict-first
        }
    }
}

// =====================================================================
// Kernel 3: persistent bidirectional LSTM recurrence.
// grid (64, 2): 64 blocks per direction, 64 sequences per block, 256 threads.
// Weights in smem once, c in registers, h PRE-DUPLICATED (float2(h,h)) in
// PING-PONG smem buffers: step tau reads buf[tau&1], writes buf[(tau+1)&1],
// so only ONE bar.sync per step is needed (publish-before-read).
// G loads (__ldcs, consumed-once) prefetched into registers BEFORE the
// recurrent GEMM; h_all stores are __stcs (stream-once to attn kernel).
// =====================================================================
__global__ void __launch_bounds__(256, 1) lstm_seq_kernel(
    const float* __restrict__ Wf, const float* __restrict__ Wb)
{
    extern __shared__ float sm[];
    float*  s_w   = sm;                       // 64*256 = 16384 floats (64 KB)
    float2* s_hA  = (float2*)(sm + 16384);    // buf0: [64 rows][64 k] of (h,h) = 32 KB
    float2* s_hB  = s_hA + 4096;              // buf1: 32 KB  (total 128 KB dynamic)
    int tid = threadIdx.x;
    int dir = blockIdx.y;
    int seq0 = blockIdx.x * 64;
    const float* W = (dir ? Wb : Wf) + 64*256;

    for (int i = tid; i < 16384; i += 256) s_w[i] = W[i];
    for (int i = tid; i < 4096;  i += 256) s_hA[i] = make_float2(0.0f, 0.0f);

    int jc2 = (tid & 31) * 2;
    int rg  = tid >> 5;          // 0..7
    int r0  = rg * 8;            // local rows r0..r0+7

    float c0[8], c1[8];
    #pragma unroll
    for (int m=0;m<8;m++){ c0[m]=0.0f; c1[m]=0.0f; }

    __syncthreads();

    for (int tau = 0; tau < 64; ++tau){
        int t_x = dir ? (63 - tau) : tau;
        float2* h_rd = (tau & 1) ? s_hB : s_hA;
        float2* h_wr = (tau & 1) ? s_hA : s_hB;

        // ---- prefetch G for this step (independent of h; consumed once) ----
        float2 Gi[8], Gj[8], Gf[8], Go[8];
        #pragma unroll
        for (int m=0;m<8;m++){
            int row = seq0 + r0 + m;
            size_t gb = (((size_t)dir*64 + t_x)*4096 + row)*256;
            Gi[m] = __ldcs((const float2*)&g_G[gb + jc2]);
            Gj[m] = __ldcs((const float2*)&g_G[gb + 64  + jc2]);
            Gf[m] = __ldcs((const float2*)&g_G[gb + 128 + jc2]);
            Go[m] = __ldcs((const float2*)&g_G[gb + 192 + jc2]);
        }

        ull_t acc[8][4];
        #pragma unroll
        for (int m=0;m<8;m++){
            #pragma unroll
            for (int q=0;q<4;q++) acc[m][q] = 0ull;
        }

        // z_h = h @ W_h : per 2 k's, 8 weight pairs + 8 packed-h LDS.128
        #pragma unroll 2
        for (int k=0;k<64;k+=2){
            const ull_t* w0 = (const ull_t*)&s_w[(k+0)*256 + jc2];
            const ull_t* w1 = (const ull_t*)&s_w[(k+1)*256 + jc2];
            ull_t wi0 = w0[0],  wi1 = w1[0];      // gate i, k / k+1
            ull_t wj0 = w0[32], wj1 = w1[32];     // +64 floats
            ull_t wf0 = w0[64], wf1 = w1[64];     // +128 floats
            ull_t wo0 = w0[96], wo1 = w1[96];     // +192 floats
            #pragma unroll
            for (int m=0;m<8;m++){
                ulonglong2 h2 = *(const ulonglong2*)&h_rd[(r0+m)*64 + k];  // broadcast
                ffma2(acc[m][0], h2.x, wi0); ffma2(acc[m][0], h2.y, wi1);
                ffma2(acc[m][1], h2.x, wj0); ffma2(acc[m][1], h2.y, wj1);
                ffma2(acc[m][2], h2.x, wf0); ffma2(acc[m][2], h2.y, wf1);
                ffma2(acc[m][3], h2.x, wo0); ffma2(acc[m][3], h2.y, wo1);
            }
        }

        #pragma unroll
        for (int m=0;m<8;m++){
            int row = seq0 + r0 + m;
            float zi0,zi1,zj0,zj1,zf0,zf1,zo0,zo1;
            upk2(acc[m][0], zi0, zi1); zi0 += Gi[m].x; zi1 += Gi[m].y;
            upk2(acc[m][1], zj0, zj1); zj0 += Gj[m].x; zj1 += Gj[m].y;
            upk2(acc[m][2], zf0, zf1); zf0 += Gf[m].x; zf1 += Gf[m].y;
            upk2(acc[m][3], zo0, zo1); zo0 += Go[m].x; zo1 += Go[m].y;

            float cc0 = c0[m]*sigm(zf0 + 1.0f) + sigm(zi0)*tanh_f(zj0);
            float cc1 = c1[m]*sigm(zf1 + 1.0f) + sigm(zi1)*tanh_f(zj1);
            c0[m] = cc0; c1[m] = cc1;
            float h0 = tanh_f(cc0)*sigm(zo0);
            float h1 = tanh_f(cc1)*sigm(zo1);

            h_wr[(r0+m)*64 + jc2]     = make_float2(h0, h0);
            h_wr[(r0+m)*64 + jc2 + 1] = make_float2(h1, h1);
            __stcs((float2*)&g_hall[((size_t)(dir*4096 + row)*64 + t_x)*64 + jc2],
                   make_float2(h0, h1));
        }
        __syncthreads();   // publish h_wr before next step reads it (single barrier/step)
    }
}

// =====================================================================
// Kernel 4: attention epilogue, 4 sequences per 256-thread block (2048 blocks).
// W3 + per-T params staged in smem once per block (4x less L2 traffic).
// Group layout: ty = tid>>6 selects the sequence slot, tx = tid&63 is the
// t-index. Each slot's h tile lives in a 65-stride padded smem slice
// (conflict-free for both the row-fill and the column-dot access patterns).
// Reductions: warp shuffles + per-slot 2-entry smem combine with uniform
// block-wide __syncthreads (all 256 threads hit every barrier).
// =====================================================================
__device__ __forceinline__ float grp_sum(float v, volatile float* s2g){
    #pragma unroll
    for (int o=16;o>0;o>>=1) v += __shfl_xor_sync(0xffffffffu, v, o);
    if ((threadIdx.x & 31)==0) s2g[(threadIdx.x>>5)&1] = v;
    __syncthreads();
    float r = s2g[0] + s2g[1];
    __syncthreads();
    return r;
}
__device__ __forceinline__ float grp_max(float v, volatile float* s2g){
    #pragma unroll
    for (int o=16;o>0;o>>=1) v = fmaxf(v, __shfl_xor_sync(0xffffffffu, v, o));
    if ((threadIdx.x & 31)==0) s2g[(threadIdx.x>>5)&1] = v;
    __syncthreads();
    float r = fmaxf(s2g[0], s2g[1]);
    __syncthreads();
    return r;
}

__global__ void __launch_bounds__(256) attn_kernel(
    const float* __restrict__ wx, const float* __restrict__ bxp,
    const float* __restrict__ wp, const float* __restrict__ bpp,
    const float* __restrict__ gp, const float* __restrict__ bep,
    const float* __restrict__ W3, const float* __restrict__ b3,
    float* __restrict__ out)
{
    extern __shared__ float smem[];
    float* sh   = smem;              // 4 slots * 64*65 = 16640 floats
    float* sW3  = sh + 16640;        // 4096
    float* swx  = sW3 + 4096;        // 64
    float* swp  = swx + 64;          // 64
    float* sgp  = swp + 64;          // 64
    float* sbep = sgp + 64;          // 64
    float* sb3  = sbep + 64;         // 64
    float* sp   = sb3 + 64;          // 4*64
    float* sxs  = sp + 256;          // 4*64
    float* s2   = sxs + 256;         // 4*2
    // total 21576 floats = 86304 B

    int tid = threadIdx.x;
    int ty = tid >> 6, tx = tid & 63;
    int s = blockIdx.x * 4 + ty;
    const float* hp = g_hall + (size_t)s*4096;

    for (int i = tid; i < 4096; i += 256) sW3[i] = W3[i];
    if (tid < 64){
        swx[tid]=wx[tid]; swp[tid]=wp[tid];
        sgp[tid]=gp[tid]; sbep[tid]=bep[tid]; sb3[tid]=b3[tid];
    }
    float bx0 = bxp[0], bp0 = bpp[0];
    float* shy = sh + ty*4160;              // 64*65 per slot
    #pragma unroll 8
    for (int t2 = 0; t2 < 64; t2++) shy[t2*65 + tx] = __ldcs(&hp[t2*64 + tx]);
    __syncthreads();

    volatile float* s2g = s2 + ty*2;

    float xv = bx0, pv = bp0;
    #pragma unroll 8
    for (int h = 0; h < 64; h++){
        float hv = shy[tx*65 + h];
        xv = fmaf(hv, swx[h], xv);
        pv = fmaf(hv, swp[h], pv);
    }
    float S = grp_sum(pv, s2g);
    float Q = grp_sum(pv*pv, s2g);
    float mean = S*(1.0f/64.0f), var = Q*(1.0f/64.0f)-mean*mean;
    float rs = rsqrtf(var + 1e-12f);
    float pn = fmaxf((pv-mean)*rs*sgp[tx] + sbep[tx], 0.0f);
    sp[ty*64+tx] = pn; sxs[ty*64+tx] = xv;
    __syncthreads();

    float l = sb3[tx];
    #pragma unroll 8
    for (int t2 = 0; t2 < 64; t2++) l = fmaf(sp[ty*64+t2], sW3[t2*64 + tx], l);
    float mx = grp_max(l, s2g);
    float e = __expf(l - mx);
    float Se = grp_sum(e, s2g);
    float val = (e/Se) * sxs[ty*64+tx];
    float tot = grp_sum(val, s2g);
    if (tx == 0) out[s] = tot;
}

// =====================================================================
extern "C" void kernel_launch(void* const* d_in, const int* in_sizes, int n_in,
                              void* d_out, int out_size)
{
    const float* obs   = (const float*)d_in[0];
    const float* action= (const float*)d_in[1];
    const float* W1 = (const float*)d_in[2];
    const float* b1 = (const float*)d_in[3];
    const float* g1 = (const float*)d_in[4];
    const float* be1= (const float*)d_in[5];
    const float* W2 = (const float*)d_in[6];
    const float* b2 = (const float*)d_in[7];
    const float* g2 = (const float*)d_in[8];
    const float* be2= (const float*)d_in[9];
    const float* Wf = (const float*)d_in[10];
    const float* bf = (const float*)d_in[11];
    const float* Wb = (const float*)d_in[12];
    const float* bb = (const float*)d_in[13];
    const float* wx = (const float*)d_in[14];
    const float* bx = (const float*)d_in[15];
    const float* wp = (const float*)d_in[16];
    const float* bp = (const float*)d_in[17];
    const float* gp = (const float*)d_in[18];
    const float* bep= (const float*)d_in[19];
    const float* W3 = (const float*)d_in[20];
    const float* b3 = (const float*)d_in[21];
    float* out = (float*)d_out;

    cudaFuncSetAttribute(mlp_kernel,      cudaFuncAttributeMaxDynamicSharedMemorySize, 87552);
    cudaFuncSetAttribute(lstm_seq_kernel, cudaFuncAttributeMaxDynamicSharedMemorySize, 131072);
    cudaFuncSetAttribute(attn_kernel,     cudaFuncAttributeMaxDynamicSharedMemorySize, 86304);

    mlp_kernel<<<4096, 256, 87552>>>(obs, action, W1,b1,g1,be1, W2,b2,g2,be2);
    gemm_g_kernel<<<dim3(4096,2), 256>>>(Wf, bf, Wb, bb);
    lstm_seq_kernel<<<dim3(64,2), 256, 131072>>>(Wf, Wb);
    attn_kernel<<<2048, 256, 86304>>>(wx, bx, wp, bp, gp, bep, W3, b3, out);
}

// round 15
// speedup vs baseline: 1.6364x; 1.6364x over previous
#include <cuda_runtime.h>
#include <math.h>

#define Bn 4096
#define Tn 64
#define Hn 64
#define BT (Bn*Tn)

typedef unsigned long long ull_t;

// ---------------- scratch (device globals; no allocation allowed) ----------------
__device__ float g_X[(size_t)BT*64];                 // MLP output [B*T,64], row r = b*T+t
__device__ float g_hall[(size_t)2*Bn*Tn*Hn];         // [s][t][h], s<B: fw, s>=B: bw (time-aligned)

// clamped fast activations: avoids __fdividef's undefined window (den in 2^126..2^128)
__device__ __forceinline__ float sigm(float x){
    x = fminf(fmaxf(x, -30.0f), 30.0f);
    return __fdividef(1.0f, 1.0f + __expf(-x));
}
__device__ __forceinline__ float tanh_f(float x){
    x = fminf(fmaxf(x, -15.0f), 15.0f);
    return 1.0f - __fdividef(2.0f, __expf(2.0f*x) + 1.0f);
}

// ---- packed f32x2 helpers (sm_103a) ----
__device__ __forceinline__ ull_t pk2(float lo, float hi){
    ull_t r; asm("mov.b64 %0, {%1,%2};" : "=l"(r) : "f"(lo), "f"(hi)); return r;
}
__device__ __forceinline__ void upk2(ull_t v, float &lo, float &hi){
    asm("mov.b64 {%0,%1}, %2;" : "=f"(lo), "=f"(hi) : "l"(v));
}
__device__ __forceinline__ void ffma2(ull_t &d, ull_t a, ull_t b){
    asm("fma.rn.f32x2 %0, %1, %2, %0;" : "+l"(d) : "l"(a), "l"(b));
}

// =====================================================================
// Kernel 1: fused MLP trunk (unchanged from the R13 passing version)
// =====================================================================
__global__ void __launch_bounds__(256) mlp_kernel(
    const float* __restrict__ obs, const float* __restrict__ action,
    const float* __restrict__ W1, const float* __restrict__ b1, const float* __restrict__ gm1, const float* __restrict__ be1,
    const float* __restrict__ W2, const float* __restrict__ b2, const float* __restrict__ gm2, const float* __restrict__ be2)
{
    extern __shared__ float sm[];
    float*  s_W1  = sm;                     // 128*64 = 8192 floats
    float*  s_W2  = s_W1 + 8192;            // 96*64  = 6144
    float*  s_p   = s_W2 + 6144;            // 6*64   = 384
    float2* s_ob2 = (float2*)(s_p + 384);   // 16*128 float2 = 4096 floats
    float2* s_in2 = s_ob2 + 2048;           // 16*96  float2 = 3072 floats
    // total 21888 floats = 87552 B

    int tid = threadIdx.x;
    for (int i = tid; i < 8192; i += 256) s_W1[i] = W1[i];
    for (int i = tid; i < 6144; i += 256) s_W2[i] = W2[i];
    if (tid < 64) {
        s_p[tid]     = b1[tid];  s_p[64+tid]  = gm1[tid]; s_p[128+tid] = be1[tid];
        s_p[192+tid] = b2[tid];  s_p[256+tid] = gm2[tid]; s_p[320+tid] = be2[tid];
    }
    __syncthreads();

    int lane = tid & 31, w = tid >> 5;
    int j2 = lane * 2;
    int r0 = w * 2;

    for (int it = 0; it < 4; ++it) {
        int rowbase = blockIdx.x * 64 + it * 16;
        if (it) __syncthreads();
        for (int i = tid; i < 2048; i += 256){
            float v = obs[(size_t)rowbase*128 + i];
            s_ob2[i] = make_float2(v, v);
        }
        for (int i = tid; i < 512;  i += 256){
            float v = action[(size_t)rowbase*32 + i];
            s_in2[(i>>5)*96 + 64 + (i&31)] = make_float2(v, v);
        }
        __syncthreads();

        // ---- layer 1 ----
        ull_t acc0 = pk2(s_p[j2], s_p[j2+1]);
        ull_t acc1 = acc0;
        const float2* a0p = &s_ob2[r0*128];
        const float2* a1p = &s_ob2[(r0+1)*128];
        #pragma unroll 8
        for (int k = 0; k < 128; k += 2){
            ulonglong2 a0 = *(const ulonglong2*)&a0p[k];
            ulonglong2 a1 = *(const ulonglong2*)&a1p[k];
            ull_t w0 = *(const ull_t*)&s_W1[(k+0)*64 + j2];
            ull_t w1 = *(const ull_t*)&s_W1[(k+1)*64 + j2];
            ffma2(acc0, a0.x, w0); ffma2(acc1, a1.x, w0);
            ffma2(acc0, a0.y, w1); ffma2(acc1, a1.y, w1);
        }
        {
            float v00,v01,v10,v11;
            upk2(acc0,v00,v01); upk2(acc1,v10,v11);
            float s0=v00+v01, q0=v00*v00+v01*v01;
            float s1=v10+v11, q1=v10*v10+v11*v11;
            #pragma unroll
            for (int o=16;o>0;o>>=1){
                s0+=__shfl_xor_sync(0xffffffffu,s0,o); q0+=__shfl_xor_sync(0xffffffffu,q0,o);
                s1+=__shfl_xor_sync(0xffffffffu,s1,o); q1+=__shfl_xor_sync(0xffffffffu,q1,o);
            }
            float m0=s0*(1.0f/64.0f), var0=q0*(1.0f/64.0f)-m0*m0, rs0=rsqrtf(var0+1e-12f);
            float m1=s1*(1.0f/64.0f), var1=q1*(1.0f/64.0f)-m1*m1, rs1=rsqrtf(var1+1e-12f);
            float ga=s_p[64+j2], gb=s_p[64+j2+1], ba=s_p[128+j2], bbv=s_p[128+j2+1];
            float o00 = fmaxf((v00-m0)*rs0*ga+ba,0.0f), o01 = fmaxf((v01-m0)*rs0*gb+bbv,0.0f);
            float o10 = fmaxf((v10-m1)*rs1*ga+ba,0.0f), o11 = fmaxf((v11-m1)*rs1*gb+bbv,0.0f);
            *(float4*)&s_in2[r0*96 + j2]     = make_float4(o00,o00,o01,o01);
            *(float4*)&s_in2[(r0+1)*96 + j2] = make_float4(o10,o10,o11,o11);
        }
        __syncwarp();

        // ---- layer 2 ----
        acc0 = pk2(s_p[192+j2], s_p[192+j2+1]);
        acc1 = acc0;
        const float2* i0p = &s_in2[r0*96];
        const float2* i1p = &s_in2[(r0+1)*96];
        #pragma unroll 8
        for (int k = 0; k < 96; k += 2){
            ulonglong2 a0 = *(const ulonglong2*)&i0p[k];
            ulonglong2 a1 = *(const ulonglong2*)&i1p[k];
            ull_t w0 = *(const ull_t*)&s_W2[(k+0)*64 + j2];
            ull_t w1 = *(const ull_t*)&s_W2[(k+1)*64 + j2];
            ffma2(acc0, a0.x, w0); ffma2(acc1, a1.x, w0);
            ffma2(acc0, a0.y, w1); ffma2(acc1, a1.y, w1);
        }
        {
            float v00,v01,v10,v11;
            upk2(acc0,v00,v01); upk2(acc1,v10,v11);
            float s0=v00+v01, q0=v00*v00+v01*v01;
            float s1=v10+v11, q1=v10*v10+v11*v11;
            #pragma unroll
            for (int o=16;o>0;o>>=1){
                s0+=__shfl_xor_sync(0xffffffffu,s0,o); q0+=__shfl_xor_sync(0xffffffffu,q0,o);
                s1+=__shfl_xor_sync(0xffffffffu,s1,o); q1+=__shfl_xor_sync(0xffffffffu,q1,o);
            }
            float m0=s0*(1.0f/64.0f), var0=q0*(1.0f/64.0f)-m0*m0, rs0=rsqrtf(var0+1e-12f);
            float m1=s1*(1.0f/64.0f), var1=q1*(1.0f/64.0f)-m1*m1, rs1=rsqrtf(var1+1e-12f);
            float ga=s_p[256+j2], gb=s_p[256+j2+1], ba=s_p[320+j2], bbv=s_p[320+j2+1];
            float2 o0 = make_float2(fmaxf((v00-m0)*rs0*ga+ba,0.0f), fmaxf((v01-m0)*rs0*gb+bbv,0.0f));
            float2 o1 = make_float2(fmaxf((v10-m1)*rs1*ga+ba,0.0f), fmaxf((v11-m1)*rs1*gb+bbv,0.0f));
            *(float2*)&g_X[(size_t)(rowbase + r0)*64 + j2]     = o0;
            *(float2*)&g_X[(size_t)(rowbase + r0 + 1)*64 + j2] = o1;
        }
    }
}

// =====================================================================
// Kernel 2: FUSED persistent bidirectional LSTM.
// z_t = x_t @ W[0:64] + h_{t-1} @ W[64:128] + bias   -- no g_G intermediate!
// Removes the 536 MB G write + 536 MB G read (~750 us of DRAM time at the
// measured ~1.4 TB/s effective bandwidth) at the cost of ~+300 us FFMA2.
// grid (64, 2): 64 blocks/dir, 64 sequences/block, 256 threads (8 rows ea).
// smem: full W (128 KB) + h dup buffer (32 KB) + 2x ping-pong x dup (64 KB)
//     = 224 KB, 1 CTA/SM. x_{t+1} prefetched during step t's FMA loop.
// 2 barriers/step. c in registers.
// =====================================================================
__global__ void __launch_bounds__(256, 1) lstm_fused_kernel(
    const float* __restrict__ Wf, const float* __restrict__ bfv,
    const float* __restrict__ Wb, const float* __restrict__ bbv)
{
    extern __shared__ float smbase[];
    float*  s_w  = smbase;                     // 128*256 = 32768 floats (128 KB)
    float2* s_h2 = (float2*)(smbase + 32768);  // 64x64 of (h,h) = 32 KB
    float2* s_x2 = s_h2 + 4096;                // 2 bufs x 64x64 of (x,x) = 64 KB
    int tid = threadIdx.x;
    int dir = blockIdx.y;
    int seq0 = blockIdx.x * 64;
    const float* W    = dir ? Wb : Wf;
    const float* bias = dir ? bbv : bfv;

    for (int i = tid; i < 32768; i += 256) s_w[i] = W[i];
    for (int i = tid; i < 4096;  i += 256) s_h2[i] = make_float2(0.0f, 0.0f);

    int jc2 = (tid & 31) * 2;
    int rg  = tid >> 5;          // 0..7
    int r0  = rg * 8;            // local rows r0..r0+7

    // bias pairs for this thread's gate columns
    float2 Bi = *(const float2*)&bias[jc2];
    float2 Bj = *(const float2*)&bias[64  + jc2];
    float2 Bf = *(const float2*)&bias[128 + jc2];
    float2 Bo = *(const float2*)&bias[192 + jc2];

    float c0[8], c1[8];
    #pragma unroll
    for (int m=0;m<8;m++){ c0[m]=0.0f; c1[m]=0.0f; }

    // ---- preload x for tau=0 into buffer 0 ----
    {
        int t_x = dir ? 63 : 0;
        int row = tid >> 2;           // 0..63
        int cb  = (tid & 3) * 16;     // 0,16,32,48
        const float4* src = (const float4*)&g_X[((size_t)((seq0+row)*64 + t_x))*64 + cb];
        float4 a = src[0], b = src[1], c = src[2], d = src[3];
        float4* q = (float4*)&s_x2[row*64 + cb];
        q[0]=make_float4(a.x,a.x,a.y,a.y); q[1]=make_float4(a.z,a.z,a.w,a.w);
        q[2]=make_float4(b.x,b.x,b.y,b.y); q[3]=make_float4(b.z,b.z,b.w,b.w);
        q[4]=make_float4(c.x,c.x,c.y,c.y); q[5]=make_float4(c.z,c.z,c.w,c.w);
        q[6]=make_float4(d.x,d.x,d.y,d.y); q[7]=make_float4(d.z,d.z,d.w,d.w);
    }
    __syncthreads();

    for (int tau = 0; tau < 64; ++tau){
        int t_x = dir ? (63 - tau) : tau;
        const float2* xcur = s_x2 + (tau & 1) * 4096;

        // ---- prefetch x for step tau+1 into the other buffer ----
        if (tau < 63){
            int t_n = dir ? (63 - (tau+1)) : (tau+1);
            int row = tid >> 2;
            int cb  = (tid & 3) * 16;
            const float4* src = (const float4*)&g_X[((size_t)((seq0+row)*64 + t_n))*64 + cb];
            float4 a = src[0], b = src[1], c = src[2], d = src[3];
            float4* q = (float4*)&((float2*)(s_x2 + ((tau+1)&1)*4096))[row*64 + cb];
            q[0]=make_float4(a.x,a.x,a.y,a.y); q[1]=make_float4(a.z,a.z,a.w,a.w);
            q[2]=make_float4(b.x,b.x,b.y,b.y); q[3]=make_float4(b.z,b.z,b.w,b.w);
            q[4]=make_float4(c.x,c.x,c.y,c.y); q[5]=make_float4(c.z,c.z,c.w,c.w);
            q[6]=make_float4(d.x,d.x,d.y,d.y); q[7]=make_float4(d.z,d.z,d.w,d.w);
        }

        ull_t acc[8][4];
        #pragma unroll
        for (int m=0;m<8;m++){
            #pragma unroll
            for (int q=0;q<4;q++) acc[m][q] = 0ull;
        }

        // ---- x part: z += x_t @ W[0:64]  (weight rows 0..63) ----
        #pragma unroll 2
        for (int k=0;k<64;k+=2){
            const ull_t* w0 = (const ull_t*)&s_w[(k+0)*256 + jc2];
            const ull_t* w1 = (const ull_t*)&s_w[(k+1)*256 + jc2];
            ull_t wi0 = w0[0],  wi1 = w1[0];
            ull_t wj0 = w0[32], wj1 = w1[32];
            ull_t wf0 = w0[64], wf1 = w1[64];
            ull_t wo0 = w0[96], wo1 = w1[96];
            #pragma unroll
            for (int m=0;m<8;m++){
                ulonglong2 a2 = *(const ulonglong2*)&xcur[(r0+m)*64 + k];
                ffma2(acc[m][0], a2.x, wi0); ffma2(acc[m][0], a2.y, wi1);
                ffma2(acc[m][1], a2.x, wj0); ffma2(acc[m][1], a2.y, wj1);
                ffma2(acc[m][2], a2.x, wf0); ffma2(acc[m][2], a2.y, wf1);
                ffma2(acc[m][3], a2.x, wo0); ffma2(acc[m][3], a2.y, wo1);
            }
        }
        // ---- h part: z += h @ W[64:128]  (weight rows 64..127) ----
        #pragma unroll 2
        for (int k=0;k<64;k+=2){
            const ull_t* w0 = (const ull_t*)&s_w[(64+k+0)*256 + jc2];
            const ull_t* w1 = (const ull_t*)&s_w[(64+k+1)*256 + jc2];
            ull_t wi0 = w0[0],  wi1 = w1[0];
            ull_t wj0 = w0[32], wj1 = w1[32];
            ull_t wf0 = w0[64], wf1 = w1[64];
            ull_t wo0 = w0[96], wo1 = w1[96];
            #pragma unroll
            for (int m=0;m<8;m++){
                ulonglong2 h2 = *(const ulonglong2*)&s_h2[(r0+m)*64 + k];
                ffma2(acc[m][0], h2.x, wi0); ffma2(acc[m][0], h2.y, wi1);
                ffma2(acc[m][1], h2.x, wj0); ffma2(acc[m][1], h2.y, wj1);
                ffma2(acc[m][2], h2.x, wf0); ffma2(acc[m][2], h2.y, wf1);
                ffma2(acc[m][3], h2.x, wo0); ffma2(acc[m][3], h2.y, wo1);
            }
        }
        __syncthreads();   // s_h2 / xcur reads complete; xnext stores published

        #pragma unroll
        for (int m=0;m<8;m++){
            int row = seq0 + r0 + m;
            float zi0,zi1,zj0,zj1,zf0,zf1,zo0,zo1;
            upk2(acc[m][0], zi0, zi1); zi0 += Bi.x; zi1 += Bi.y;
            upk2(acc[m][1], zj0, zj1); zj0 += Bj.x; zj1 += Bj.y;
            upk2(acc[m][2], zf0, zf1); zf0 += Bf.x; zf1 += Bf.y;
            upk2(acc[m][3], zo0, zo1); zo0 += Bo.x; zo1 += Bo.y;

            float cc0 = c0[m]*sigm(zf0 + 1.0f) + sigm(zi0)*tanh_f(zj0);
            float cc1 = c1[m]*sigm(zf1 + 1.0f) + sigm(zi1)*tanh_f(zj1);
            c0[m] = cc0; c1[m] = cc1;
            float h0 = tanh_f(cc0)*sigm(zo0);
            float h1 = tanh_f(cc1)*sigm(zo1);

            s_h2[(r0+m)*64 + jc2]     = make_float2(h0, h0);
            s_h2[(r0+m)*64 + jc2 + 1] = make_float2(h1, h1);
            __stcs((float2*)&g_hall[((size_t)(dir*4096 + row)*64 + t_x)*64 + jc2],
                   make_float2(h0, h1));
        }
        __syncthreads();   // publish new h before next step reads it
    }
}

// =====================================================================
// Kernel 3: attention epilogue (unchanged from the R13 passing version)
// =====================================================================
__device__ __forceinline__ float grp_sum(float v, volatile float* s2g){
    #pragma unroll
    for (int o=16;o>0;o>>=1) v += __shfl_xor_sync(0xffffffffu, v, o);
    if ((threadIdx.x & 31)==0) s2g[(threadIdx.x>>5)&1] = v;
    __syncthreads();
    float r = s2g[0] + s2g[1];
    __syncthreads();
    return r;
}
__device__ __forceinline__ float grp_max(float v, volatile float* s2g){
    #pragma unroll
    for (int o=16;o>0;o>>=1) v = fmaxf(v, __shfl_xor_sync(0xffffffffu, v, o));
    if ((threadIdx.x & 31)==0) s2g[(threadIdx.x>>5)&1] = v;
    __syncthreads();
    float r = fmaxf(s2g[0], s2g[1]);
    __syncthreads();
    return r;
}

__global__ void __launch_bounds__(256) attn_kernel(
    const float* __restrict__ wx, const float* __restrict__ bxp,
    const float* __restrict__ wp, const float* __restrict__ bpp,
    const float* __restrict__ gp, const float* __restrict__ bep,
    const float* __restrict__ W3, const float* __restrict__ b3,
    float* __restrict__ out)
{
    extern __shared__ float smem[];
    float* sh   = smem;              // 4 slots * 64*65 = 16640 floats
    float* sW3  = sh + 16640;        // 4096
    float* swx  = sW3 + 4096;        // 64
    float* swp  = swx + 64;          // 64
    float* sgp  = swp + 64;          // 64
    float* sbep = sgp + 64;          // 64
    float* sb3  = sbep + 64;         // 64
    float* sp   = sb3 + 64;          // 4*64
    float* sxs  = sp + 256;          // 4*64
    float* s2   = sxs + 256;         // 4*2
    // total 21576 floats = 86304 B

    int tid = threadIdx.x;
    int ty = tid >> 6, tx = tid & 63;
    int s = blockIdx.x * 4 + ty;
    const float* hp = g_hall + (size_t)s*4096;

    for (int i = tid; i < 4096; i += 256) sW3[i] = W3[i];
    if (tid < 64){
        swx[tid]=wx[tid]; swp[tid]=wp[tid];
        sgp[tid]=gp[tid]; sbep[tid]=bep[tid]; sb3[tid]=b3[tid];
    }
    float bx0 = bxp[0], bp0 = bpp[0];
    float* shy = sh + ty*4160;              // 64*65 per slot
    #pragma unroll 8
    for (int t2 = 0; t2 < 64; t2++) shy[t2*65 + tx] = __ldcs(&hp[t2*64 + tx]);
    __syncthreads();

    volatile float* s2g = s2 + ty*2;

    float xv = bx0, pv = bp0;
    #pragma unroll 8
    for (int h = 0; h < 64; h++){
        float hv = shy[tx*65 + h];
        xv = fmaf(hv, swx[h], xv);
        pv = fmaf(hv, swp[h], pv);
    }
    float S = grp_sum(pv, s2g);
    float Q = grp_sum(pv*pv, s2g);
    float mean = S*(1.0f/64.0f), var = Q*(1.0f/64.0f)-mean*mean;
    float rs = rsqrtf(var + 1e-12f);
    float pn = fmaxf((pv-mean)*rs*sgp[tx] + sbep[tx], 0.0f);
    sp[ty*64+tx] = pn; sxs[ty*64+tx] = xv;
    __syncthreads();

    float l = sb3[tx];
    #pragma unroll 8
    for (int t2 = 0; t2 < 64; t2++) l = fmaf(sp[ty*64+t2], sW3[t2*64 + tx], l);
    float mx = grp_max(l, s2g);
    float e = __expf(l - mx);
    float Se = grp_sum(e, s2g);
    float val = (e/Se) * sxs[ty*64+tx];
    float tot = grp_sum(val, s2g);
    if (tx == 0) out[s] = tot;
}

// =====================================================================
extern "C" void kernel_launch(void* const* d_in, const int* in_sizes, int n_in,
                              void* d_out, int out_size)
{
    const float* obs   = (const float*)d_in[0];
    const float* action= (const float*)d_in[1];
    const float* W1 = (const float*)d_in[2];
    const float* b1 = (const float*)d_in[3];
    const float* g1 = (const float*)d_in[4];
    const float* be1= (const float*)d_in[5];
    const float* W2 = (const float*)d_in[6];
    const float* b2 = (const float*)d_in[7];
    const float* g2 = (const float*)d_in[8];
    const float* be2= (const float*)d_in[9];
    const float* Wf = (const float*)d_in[10];
    const float* bf = (const float*)d_in[11];
    const float* Wb = (const float*)d_in[12];
    const float* bb = (const float*)d_in[13];
    const float* wx = (const float*)d_in[14];
    const float* bx = (const float*)d_in[15];
    const float* wp = (const float*)d_in[16];
    const float* bp = (const float*)d_in[17];
    const float* gp = (const float*)d_in[18];
    const float* bep= (const float*)d_in[19];
    const float* W3 = (const float*)d_in[20];
    const float* b3 = (const float*)d_in[21];
    float* out = (float*)d_out;

    cudaFuncSetAttribute(mlp_kernel,        cudaFuncAttributeMaxDynamicSharedMemorySize, 87552);
    cudaFuncSetAttribute(lstm_fused_kernel, cudaFuncAttributeMaxDynamicSharedMemorySize, 229376);
    cudaFuncSetAttribute(attn_kernel,       cudaFuncAttributeMaxDynamicSharedMemorySize, 86304);

    mlp_kernel<<<4096, 256, 87552>>>(obs, action, W1,b1,g1,be1, W2,b2,g2,be2);
    lstm_fused_kernel<<<dim3(64,2), 256, 229376>>>(Wf, bf, Wb, bb);
    attn_kernel<<<2048, 256, 86304>>>(wx, bx, wp, bp, gp, bep, W3, b3, out);
}